// round 2
// baseline (speedup 1.0000x reference)
#include <cuda_runtime.h>
#include <math.h>

#define B_   2
#define S_   2048
#define E_   1024
#define H_   32
#define DK_  32
#define FFN_ 4096
#define M_   (B_*S_)   // 4096 rows

// ---------------- scratch (device globals; no allocations allowed) ----------
__device__ float g_q[M_*E_];
__device__ float g_k[M_*E_];
__device__ float g_v[M_*E_];
__device__ float g_attn[M_*E_];
__device__ float g_x1[M_*E_];
__device__ float g_ffn[M_*FFN_];

// ---------------- SGEMM: C = A[M,K] @ W[K,N] + bias, optional ReLU ----------
// 128x128 tile, BK=8, 256 threads, 8x8 per-thread register tile.
// Double-buffered smem: one __syncthreads per k-slice, global loads overlapped
// with compute.
__global__ __launch_bounds__(256) void sgemm_bias_kernel(
    const float* __restrict__ A, const float* __restrict__ W,
    const float* __restrict__ bias, float* __restrict__ C,
    int M, int N, int K, int doRelu)
{
    __shared__ float As[2][8][128];
    __shared__ float Bs[2][8][128];

    const int tid = threadIdx.x;
    const int tx  = tid & 15;      // 0..15 -> N direction
    const int ty  = tid >> 4;      // 0..15 -> M direction
    const int row0 = blockIdx.y * 128;
    const int col0 = blockIdx.x * 128;

    // A tile load mapping: 128 rows x 8 cols, one float4 per thread
    const int a_row = tid >> 1;            // 0..127
    const int a_col = (tid & 1) << 2;      // 0 or 4
    // W tile load mapping: 8 rows x 128 cols, one float4 per thread
    const int b_row = tid >> 5;            // 0..7
    const int b_col = (tid & 31) << 2;     // 0..124

    const float* Aptr = A + (size_t)(row0 + a_row) * K + a_col;
    const float* Wptr = W + (size_t)b_row * N + col0 + b_col;

    float acc[8][8];
    #pragma unroll
    for (int i = 0; i < 8; i++)
        #pragma unroll
        for (int j = 0; j < 8; j++) acc[i][j] = 0.f;

    // preload slice 0 into buffer 0
    {
        float4 av = *(const float4*)(Aptr);
        As[0][a_col + 0][a_row] = av.x;
        As[0][a_col + 1][a_row] = av.y;
        As[0][a_col + 2][a_row] = av.z;
        As[0][a_col + 3][a_row] = av.w;
        *(float4*)&Bs[0][b_row][b_col] = *(const float4*)(Wptr);
    }
    __syncthreads();

    const int nT = K / 8;
    int buf = 0;
    for (int t = 0; t < nT; t++) {
        float4 av, bv4;
        const int has_next = (t + 1 < nT);
        if (has_next) {
            int k0 = (t + 1) * 8;
            av  = *(const float4*)(Aptr + k0);
            bv4 = *(const float4*)(Wptr + (size_t)k0 * N);
        }

        #pragma unroll
        for (int kk = 0; kk < 8; kk++) {
            float ar[8], br[8];
            *(float4*)(ar)     = *(const float4*)&As[buf][kk][ty << 2];
            *(float4*)(ar + 4) = *(const float4*)&As[buf][kk][(ty << 2) + 64];
            *(float4*)(br)     = *(const float4*)&Bs[buf][kk][tx << 2];
            *(float4*)(br + 4) = *(const float4*)&Bs[buf][kk][(tx << 2) + 64];
            #pragma unroll
            for (int i = 0; i < 8; i++)
                #pragma unroll
                for (int j = 0; j < 8; j++)
                    acc[i][j] = fmaf(ar[i], br[j], acc[i][j]);
        }

        if (has_next) {
            int nb = buf ^ 1;
            As[nb][a_col + 0][a_row] = av.x;
            As[nb][a_col + 1][a_row] = av.y;
            As[nb][a_col + 2][a_row] = av.z;
            As[nb][a_col + 3][a_row] = av.w;
            *(float4*)&Bs[nb][b_row][b_col] = bv4;
            __syncthreads();
            buf = nb;
        }
    }

    // epilogue: bias (+ relu), vectorized stores
    #pragma unroll
    for (int i = 0; i < 8; i++) {
        int r = row0 + (ty << 2) + (i & 3) + ((i >> 2) << 6);
        #pragma unroll
        for (int jh = 0; jh < 2; jh++) {
            int c = col0 + (tx << 2) + (jh << 6);
            float4 bv = *(const float4*)&bias[c];
            float4 o;
            o.x = acc[i][jh * 4 + 0] + bv.x;
            o.y = acc[i][jh * 4 + 1] + bv.y;
            o.z = acc[i][jh * 4 + 2] + bv.z;
            o.w = acc[i][jh * 4 + 3] + bv.w;
            if (doRelu) {
                o.x = fmaxf(o.x, 0.f); o.y = fmaxf(o.y, 0.f);
                o.z = fmaxf(o.z, 0.f); o.w = fmaxf(o.w, 0.f);
            }
            *(float4*)&C[(size_t)r * N + c] = o;
        }
    }
}

// ---------------- Flash attention with bilinear kernel scaling --------------
// sim[b,h,i,j] = sum_d (q[b,h,i,d]*kernelW[d,h]) * k[b,h,j,d]
// grid: (S/64, H, B), 256 threads. Online softmax, O in registers.
__global__ __launch_bounds__(256) void attention_kernel(
    const float* __restrict__ q, const float* __restrict__ k,
    const float* __restrict__ v, const float* __restrict__ kernelW,
    float* __restrict__ out)
{
    __shared__ float q_s[32][68];   // [d][row], padded
    __shared__ float k_s[32][68];   // [d][row], padded
    __shared__ float v_s[64][32];   // [row][d]
    __shared__ float p_s[64][68];   // [qrow][krow], padded (float4-writable)
    __shared__ float m_s[64], l_s[64], sc_s[64];

    const int tid = threadIdx.x;
    const int tx = tid & 15;        // key-col group
    const int ty = tid >> 4;        // query-row group
    const int qb = blockIdx.x, h = blockIdx.y, b = blockIdx.z;
    const size_t base = ((size_t)b * S_) * E_ + (size_t)h * DK_;

    // load & scale Q tile (64 rows x 32 dims) -> transposed smem
    #pragma unroll
    for (int it = 0; it < 2; it++) {
        int i  = tid + it * 256;            // 0..511
        int r  = i >> 3;                    // 0..63
        int d0 = (i & 7) << 2;              // 0,4,...,28
        float4 qv = *(const float4*)&q[base + (size_t)(qb * 64 + r) * E_ + d0];
        q_s[d0 + 0][r] = qv.x * kernelW[(d0 + 0) * H_ + h];
        q_s[d0 + 1][r] = qv.y * kernelW[(d0 + 1) * H_ + h];
        q_s[d0 + 2][r] = qv.z * kernelW[(d0 + 2) * H_ + h];
        q_s[d0 + 3][r] = qv.w * kernelW[(d0 + 3) * H_ + h];
    }
    if (tid < 64) { m_s[tid] = -INFINITY; l_s[tid] = 0.f; }

    float o[8];
    #pragma unroll
    for (int c = 0; c < 8; c++) o[c] = 0.f;
    const int ro = tid >> 2;          // O row owned (0..63)
    const int co = (tid & 3) << 3;    // O col base (0,8,16,24)
    __syncthreads();

    for (int j0 = 0; j0 < S_; j0 += 64) {
        // load K (transposed) and V tiles
        #pragma unroll
        for (int it = 0; it < 2; it++) {
            int i  = tid + it * 256;
            int r  = i >> 3;
            int d0 = (i & 7) << 2;
            size_t g = base + (size_t)(j0 + r) * E_ + d0;
            float4 kv = *(const float4*)&k[g];
            k_s[d0 + 0][r] = kv.x; k_s[d0 + 1][r] = kv.y;
            k_s[d0 + 2][r] = kv.z; k_s[d0 + 3][r] = kv.w;
            *(float4*)&v_s[r][d0] = *(const float4*)&v[g];
        }
        __syncthreads();

        // scores: 4x4 per thread
        float s[4][4];
        #pragma unroll
        for (int i = 0; i < 4; i++)
            #pragma unroll
            for (int j = 0; j < 4; j++) s[i][j] = 0.f;

        #pragma unroll
        for (int d = 0; d < 32; d++) {
            float qa[4], ka[4];
            *(float4*)qa = *(const float4*)&q_s[d][ty << 2];
            *(float4*)ka = *(const float4*)&k_s[d][tx << 2];
            #pragma unroll
            for (int i = 0; i < 4; i++)
                #pragma unroll
                for (int j = 0; j < 4; j++)
                    s[i][j] = fmaf(qa[i], ka[j], s[i][j]);
        }

        // online softmax bookkeeping (reduce over 16 lanes sharing a row)
        float m_old[4], m_new[4], rs[4];
        #pragma unroll
        for (int i = 0; i < 4; i++) {
            m_old[i] = m_s[(ty << 2) + i];
            float mx = fmaxf(fmaxf(s[i][0], s[i][1]), fmaxf(s[i][2], s[i][3]));
            mx = fmaxf(mx, __shfl_xor_sync(0xffffffffu, mx, 1));
            mx = fmaxf(mx, __shfl_xor_sync(0xffffffffu, mx, 2));
            mx = fmaxf(mx, __shfl_xor_sync(0xffffffffu, mx, 4));
            mx = fmaxf(mx, __shfl_xor_sync(0xffffffffu, mx, 8));
            m_new[i] = fmaxf(m_old[i], mx);
            float sum = 0.f;
            #pragma unroll
            for (int j = 0; j < 4; j++) {
                s[i][j] = __expf(s[i][j] - m_new[i]);
                sum += s[i][j];
            }
            sum += __shfl_xor_sync(0xffffffffu, sum, 1);
            sum += __shfl_xor_sync(0xffffffffu, sum, 2);
            sum += __shfl_xor_sync(0xffffffffu, sum, 4);
            sum += __shfl_xor_sync(0xffffffffu, sum, 8);
            rs[i] = sum;
            float4 pv = make_float4(s[i][0], s[i][1], s[i][2], s[i][3]);
            *(float4*)&p_s[(ty << 2) + i][tx << 2] = pv;
        }
        __syncthreads();   // all m_s reads done; p_s visible

        if (tx == 0) {
            #pragma unroll
            for (int i = 0; i < 4; i++) {
                int r = (ty << 2) + i;
                float scale = __expf(m_old[i] - m_new[i]);
                sc_s[r] = scale;
                l_s[r]  = l_s[r] * scale + rs[i];
                m_s[r]  = m_new[i];
            }
        }
        __syncthreads();   // updates visible

        // O accumulation: O[ro][co..co+7] += P[ro][:] @ V[:, co..co+7]
        float scale = sc_s[ro];
        #pragma unroll
        for (int c = 0; c < 8; c++) o[c] *= scale;
        #pragma unroll 8
        for (int j = 0; j < 64; j++) {
            float pv = p_s[ro][j];
            float4 v0 = *(const float4*)&v_s[j][co];
            float4 v1 = *(const float4*)&v_s[j][co + 4];
            o[0] = fmaf(pv, v0.x, o[0]);
            o[1] = fmaf(pv, v0.y, o[1]);
            o[2] = fmaf(pv, v0.z, o[2]);
            o[3] = fmaf(pv, v0.w, o[3]);
            o[4] = fmaf(pv, v1.x, o[4]);
            o[5] = fmaf(pv, v1.y, o[5]);
            o[6] = fmaf(pv, v1.z, o[6]);
            o[7] = fmaf(pv, v1.w, o[7]);
        }
        __syncthreads();   // done with this tile's smem
    }

    float inv = 1.f / l_s[ro];
    size_t og = base + (size_t)(qb * 64 + ro) * E_ + co;
    float4 o0 = make_float4(o[0] * inv, o[1] * inv, o[2] * inv, o[3] * inv);
    float4 o1 = make_float4(o[4] * inv, o[5] * inv, o[6] * inv, o[7] * inv);
    *(float4*)&out[og]     = o0;
    *(float4*)&out[og + 4] = o1;
}

// ---------------- fused residual + LayerNorm --------------------------------
// y = LN(x + r) * g + beta, one block per row of E_=1024, 256 threads x4 elems
__global__ __launch_bounds__(256) void ln_residual_kernel(
    const float* __restrict__ x, const float* __restrict__ r,
    const float* __restrict__ g, const float* __restrict__ beta,
    float* __restrict__ y)
{
    __shared__ float red[256];
    const int row = blockIdx.x;
    const int tid = threadIdx.x;
    const size_t off = (size_t)row * E_;
    const int c4 = tid << 2;

    float4 xv = *(const float4*)&x[off + c4];
    float4 rv = *(const float4*)&r[off + c4];
    float v0 = xv.x + rv.x, v1 = xv.y + rv.y, v2 = xv.z + rv.z, v3 = xv.w + rv.w;

    red[tid] = v0 + v1 + v2 + v3;
    __syncthreads();
    #pragma unroll
    for (int st = 128; st > 0; st >>= 1) {
        if (tid < st) red[tid] += red[tid + st];
        __syncthreads();
    }
    float mean = red[0] * (1.f / E_);
    __syncthreads();

    float d0 = v0 - mean, d1 = v1 - mean, d2 = v2 - mean, d3 = v3 - mean;
    red[tid] = d0 * d0 + d1 * d1 + d2 * d2 + d3 * d3;
    __syncthreads();
    #pragma unroll
    for (int st = 128; st > 0; st >>= 1) {
        if (tid < st) red[tid] += red[tid + st];
        __syncthreads();
    }
    float rstd = rsqrtf(red[0] * (1.f / E_) + 1e-5f);

    float4 gv = *(const float4*)&g[c4];
    float4 bv = *(const float4*)&beta[c4];
    float4 o;
    o.x = d0 * rstd * gv.x + bv.x;
    o.y = d1 * rstd * gv.y + bv.y;
    o.z = d2 * rstd * gv.z + bv.z;
    o.w = d3 * rstd * gv.w + bv.w;
    *(float4*)&y[off + c4] = o;
}

// ---------------- launcher ---------------------------------------------------
extern "C" void kernel_launch(void* const* d_in, const int* in_sizes, int n_in,
                              void* d_out, int out_size)
{
    const float* x   = (const float*)d_in[0];
    const float* Wq  = (const float*)d_in[1];
    const float* bq  = (const float*)d_in[2];
    const float* Wk  = (const float*)d_in[3];
    const float* bk  = (const float*)d_in[4];
    const float* Wv  = (const float*)d_in[5];
    const float* bv  = (const float*)d_in[6];
    const float* kW  = (const float*)d_in[7];
    const float* Wo  = (const float*)d_in[8];
    const float* bo  = (const float*)d_in[9];
    const float* W1  = (const float*)d_in[10];
    const float* b1  = (const float*)d_in[11];
    const float* W2  = (const float*)d_in[12];
    const float* b2  = (const float*)d_in[13];
    const float* g1  = (const float*)d_in[14];
    const float* be1 = (const float*)d_in[15];
    const float* g2  = (const float*)d_in[16];
    const float* be2 = (const float*)d_in[17];
    float* out = (float*)d_out;

    float *q, *k, *v, *attn, *x1, *ffn;
    cudaGetSymbolAddress((void**)&q,    g_q);
    cudaGetSymbolAddress((void**)&k,    g_k);
    cudaGetSymbolAddress((void**)&v,    g_v);
    cudaGetSymbolAddress((void**)&attn, g_attn);
    cudaGetSymbolAddress((void**)&x1,   g_x1);
    cudaGetSymbolAddress((void**)&ffn,  g_ffn);

    dim3 gE(E_ / 128, M_ / 128);     // N=1024 GEMMs
    dim3 gF(FFN_ / 128, M_ / 128);   // N=4096 GEMM

    // QKV projections
    sgemm_bias_kernel<<<gE, 256>>>(x, Wq, bq, q, M_, E_, E_, 0);
    sgemm_bias_kernel<<<gE, 256>>>(x, Wk, bk, k, M_, E_, E_, 0);
    sgemm_bias_kernel<<<gE, 256>>>(x, Wv, bv, v, M_, E_, E_, 0);

    // bilinear-kernel flash attention -> [B,S,E] layout directly
    attention_kernel<<<dim3(S_ / 64, H_, B_), 256>>>(q, k, v, kW, attn);

    // output projection (reuse q as scratch)
    sgemm_bias_kernel<<<gE, 256>>>(attn, Wo, bo, q, M_, E_, E_, 0);

    // residual + LN 1
    ln_residual_kernel<<<M_, 256>>>(x, q, g1, be1, x1);

    // FFN
    sgemm_bias_kernel<<<gF, 256>>>(x1, W1, b1, ffn, M_, FFN_, E_, 1);
    sgemm_bias_kernel<<<gE, 256>>>(ffn, W2, b2, k, M_, E_, FFN_, 0);

    // residual + LN 2 -> final output
    ln_residual_kernel<<<M_, 256>>>(x1, k, g2, be2, out);
}

// round 3
// speedup vs baseline: 1.2602x; 1.2602x over previous
#include <cuda_runtime.h>
#include <math.h>

#define B_   2
#define S_   2048
#define E_   1024
#define H_   32
#define DK_  32
#define FFN_ 4096
#define M_   (B_*S_)   // 4096 rows

// ---------------- scratch (device globals; no allocations allowed) ----------
__device__ float g_q[M_*E_];
__device__ float g_k[M_*E_];
__device__ float g_v[M_*E_];
__device__ float g_attn[M_*E_];
__device__ float g_x1[M_*E_];
__device__ float g_ffn[M_*FFN_];

// ---------------- packed f32x2 helpers (sm_100a) ----------------------------
__device__ __forceinline__ unsigned long long fma2(unsigned long long a,
                                                   unsigned long long b,
                                                   unsigned long long c) {
    unsigned long long d;
    asm("fma.rn.f32x2 %0, %1, %2, %3;" : "=l"(d) : "l"(a), "l"(b), "l"(c));
    return d;
}
__device__ __forceinline__ unsigned long long mul2(unsigned long long a,
                                                   unsigned long long b) {
    unsigned long long d;
    asm("mul.rn.f32x2 %0, %1, %2;" : "=l"(d) : "l"(a), "l"(b));
    return d;
}
__device__ __forceinline__ unsigned long long dup2(float x) {
    unsigned long long d;
    asm("mov.b64 %0, {%1, %1};" : "=l"(d) : "f"(x));
    return d;
}
__device__ __forceinline__ float2 upk(unsigned long long v) {
    float2 r;
    asm("mov.b64 {%0, %1}, %2;" : "=f"(r.x), "=f"(r.y) : "l"(v));
    return r;
}

// ---------------- SGEMM body: C = A[M,K] @ W[K,N] + bias, optional ReLU -----
// 128x128 tile, BK=8, 256 threads, 8x8 per-thread tile held as 4x8 f32x2
// accumulators (rows paired). Double-buffered smem. FFMA2 inner loop.
__device__ __forceinline__ void sgemm_body(
    const float* __restrict__ A, const float* __restrict__ W,
    const float* __restrict__ bias, float* __restrict__ C,
    int N, int K, int doRelu)
{
    __shared__ __align__(16) float As[2][8][128];
    __shared__ __align__(16) float Bs[2][8][128];

    const int tid = threadIdx.x;
    const int tx  = tid & 15;      // N direction
    const int ty  = tid >> 4;      // M direction
    const int row0 = blockIdx.y * 128;
    const int col0 = blockIdx.x * 128;

    const int a_row = tid >> 1;            // 0..127
    const int a_col = (tid & 1) << 2;      // 0 or 4
    const int b_row = tid >> 5;            // 0..7
    const int b_col = (tid & 31) << 2;     // 0..124

    const float* Aptr = A + (size_t)(row0 + a_row) * K + a_col;
    const float* Wptr = W + (size_t)b_row * N + col0 + b_col;

    // acc2[p][j]: p = row pair (lo,hi rows), j = col index 0..7
    unsigned long long acc2[4][8];
    #pragma unroll
    for (int p = 0; p < 4; p++)
        #pragma unroll
        for (int j = 0; j < 8; j++) acc2[p][j] = 0ull;

    {   // preload slice 0
        float4 av = *(const float4*)(Aptr);
        As[0][a_col + 0][a_row] = av.x;
        As[0][a_col + 1][a_row] = av.y;
        As[0][a_col + 2][a_row] = av.z;
        As[0][a_col + 3][a_row] = av.w;
        *(float4*)&Bs[0][b_row][b_col] = *(const float4*)(Wptr);
    }
    __syncthreads();

    const int nT = K / 8;
    int buf = 0;
    for (int t = 0; t < nT; t++) {
        float4 av, bv4;
        const int has_next = (t + 1 < nT);
        if (has_next) {
            int k0 = (t + 1) * 8;
            av  = *(const float4*)(Aptr + k0);
            bv4 = *(const float4*)(Wptr + (size_t)k0 * N);
        }

        #pragma unroll
        for (int kk = 0; kk < 8; kk++) {
            ulonglong2 a0 = *(const ulonglong2*)&As[buf][kk][ty << 2];
            ulonglong2 a1 = *(const ulonglong2*)&As[buf][kk][(ty << 2) + 64];
            float br[8];
            *(float4*)(br)     = *(const float4*)&Bs[buf][kk][tx << 2];
            *(float4*)(br + 4) = *(const float4*)&Bs[buf][kk][(tx << 2) + 64];
            unsigned long long ap0 = a0.x, ap1 = a0.y, ap2 = a1.x, ap3 = a1.y;
            #pragma unroll
            for (int j = 0; j < 8; j++) {
                unsigned long long bb = dup2(br[j]);
                acc2[0][j] = fma2(ap0, bb, acc2[0][j]);
                acc2[1][j] = fma2(ap1, bb, acc2[1][j]);
                acc2[2][j] = fma2(ap2, bb, acc2[2][j]);
                acc2[3][j] = fma2(ap3, bb, acc2[3][j]);
            }
        }

        if (has_next) {
            int nb = buf ^ 1;
            As[nb][a_col + 0][a_row] = av.x;
            As[nb][a_col + 1][a_row] = av.y;
            As[nb][a_col + 2][a_row] = av.z;
            As[nb][a_col + 3][a_row] = av.w;
            *(float4*)&Bs[nb][b_row][b_col] = bv4;
            __syncthreads();
            buf = nb;
        }
    }

    // epilogue: pair p covers rows base_r (lo) and base_r+1 (hi)
    #pragma unroll
    for (int p = 0; p < 4; p++) {
        int base_r = row0 + (ty << 2) + ((p & 1) << 1) + ((p >> 1) << 6);
        float2 cp[8];
        #pragma unroll
        for (int j = 0; j < 8; j++) cp[j] = upk(acc2[p][j]);
        #pragma unroll
        for (int half = 0; half < 2; half++) {
            int r = base_r + half;
            #pragma unroll
            for (int jh = 0; jh < 2; jh++) {
                int c = col0 + (tx << 2) + (jh << 6);
                float4 bv = *(const float4*)&bias[c];
                float4 o;
                float e0 = half ? cp[jh*4+0].y : cp[jh*4+0].x;
                float e1 = half ? cp[jh*4+1].y : cp[jh*4+1].x;
                float e2 = half ? cp[jh*4+2].y : cp[jh*4+2].x;
                float e3 = half ? cp[jh*4+3].y : cp[jh*4+3].x;
                o.x = e0 + bv.x; o.y = e1 + bv.y;
                o.z = e2 + bv.z; o.w = e3 + bv.w;
                if (doRelu) {
                    o.x = fmaxf(o.x, 0.f); o.y = fmaxf(o.y, 0.f);
                    o.z = fmaxf(o.z, 0.f); o.w = fmaxf(o.w, 0.f);
                }
                *(float4*)&C[(size_t)r * N + c] = o;
            }
        }
    }
}

__global__ __launch_bounds__(256) void sgemm_bias_kernel(
    const float* __restrict__ A, const float* __restrict__ W,
    const float* __restrict__ bias, float* __restrict__ C,
    int N, int K, int doRelu)
{
    sgemm_body(A, W, bias, C, N, K, doRelu);
}

// merged QKV: blockIdx.z picks which projection
__global__ __launch_bounds__(256) void qkv_kernel(
    const float* __restrict__ x,
    const float* __restrict__ Wq, const float* __restrict__ bq, float* __restrict__ q,
    const float* __restrict__ Wk, const float* __restrict__ bk, float* __restrict__ k,
    const float* __restrict__ Wv, const float* __restrict__ bv, float* __restrict__ v)
{
    const float* W; const float* b; float* C;
    if (blockIdx.z == 0)      { W = Wq; b = bq; C = q; }
    else if (blockIdx.z == 1) { W = Wk; b = bk; C = k; }
    else                      { W = Wv; b = bv; C = v; }
    sgemm_body(x, W, b, C, E_, E_, 0);
}

// ---------------- Flash attention with bilinear kernel scaling --------------
// sim[b,h,i,j] = sum_d (q[b,h,i,d]*kernelW[d,h]) * k[b,h,j,d]
// grid: (S/64, H, B), 256 threads. 64q x 64k tiles, online softmax.
// PV phase: j-dim split across 2 thread halves, deferred reduction at end.
#define PST 67   // p_s row stride (floats), scalar access, ~conflict-free
#define VST 36   // v_s row stride

__global__ __launch_bounds__(256) void attention_kernel(
    const float* __restrict__ q, const float* __restrict__ k,
    const float* __restrict__ v, const float* __restrict__ kernelW,
    float* __restrict__ out)
{
    __shared__ __align__(16) float q_s[32][68];   // [d][row]
    __shared__ __align__(16) float k_s[32][68];   // [d][row]
    __shared__ __align__(16) float v_s[64][VST];  // [j][d]
    __shared__ __align__(16) float p_s[64 * PST]; // [row*PST + j]; reused as o_red
    __shared__ float m_s[64], l_s[64], sc_s[64];

    const int tid = threadIdx.x;
    const int tx = tid & 15;        // key-col group (softmax phase)
    const int ty = tid >> 4;        // query-row group (softmax phase)
    // PV-phase roles
    const int jh = tid >> 7;            // 0/1: which 32-key half
    const int cg = (tid >> 5) & 3;      // col group: cols cg*8..cg*8+7
    const int rp = tid & 31;            // row pair: rows 2rp, 2rp+1

    const int qb = blockIdx.x, h = blockIdx.y, b = blockIdx.z;
    const size_t base = ((size_t)b * S_) * E_ + (size_t)h * DK_;

    // load & scale Q tile (64 rows x 32 dims) -> transposed smem
    #pragma unroll
    for (int it = 0; it < 2; it++) {
        int i  = tid + it * 256;            // 0..511
        int r  = i >> 3;                    // 0..63
        int d0 = (i & 7) << 2;              // 0,4,...,28
        float4 qv = *(const float4*)&q[base + (size_t)(qb * 64 + r) * E_ + d0];
        q_s[d0 + 0][r] = qv.x * kernelW[(d0 + 0) * H_ + h];
        q_s[d0 + 1][r] = qv.y * kernelW[(d0 + 1) * H_ + h];
        q_s[d0 + 2][r] = qv.z * kernelW[(d0 + 2) * H_ + h];
        q_s[d0 + 3][r] = qv.w * kernelW[(d0 + 3) * H_ + h];
    }
    if (tid < 64) { m_s[tid] = -INFINITY; l_s[tid] = 0.f; }

    // O partial accumulators: 2 rows x 8 cols as f32x2 pairs along cols
    unsigned long long o2[2][4];
    #pragma unroll
    for (int r = 0; r < 2; r++)
        #pragma unroll
        for (int c = 0; c < 4; c++) o2[r][c] = 0ull;

    __syncthreads();

    for (int j0 = 0; j0 < S_; j0 += 64) {
        // load K (transposed) and V tiles
        #pragma unroll
        for (int it = 0; it < 2; it++) {
            int i  = tid + it * 256;
            int r  = i >> 3;
            int d0 = (i & 7) << 2;
            size_t g = base + (size_t)(j0 + r) * E_ + d0;
            float4 kv = *(const float4*)&k[g];
            k_s[d0 + 0][r] = kv.x; k_s[d0 + 1][r] = kv.y;
            k_s[d0 + 2][r] = kv.z; k_s[d0 + 3][r] = kv.w;
            *(float4*)&v_s[r][d0] = *(const float4*)&v[g];
        }
        __syncthreads();

        // scores: 4 rows x 4 keys per thread, FFMA2 over key pairs
        unsigned long long s2[4][2];
        #pragma unroll
        for (int i = 0; i < 4; i++) { s2[i][0] = 0ull; s2[i][1] = 0ull; }

        #pragma unroll
        for (int d = 0; d < 32; d++) {
            float qa[4];
            *(float4*)qa = *(const float4*)&q_s[d][ty << 2];
            ulonglong2 kp = *(const ulonglong2*)&k_s[d][tx << 2];
            #pragma unroll
            for (int i = 0; i < 4; i++) {
                unsigned long long qq = dup2(qa[i]);
                s2[i][0] = fma2(kp.x, qq, s2[i][0]);
                s2[i][1] = fma2(kp.y, qq, s2[i][1]);
            }
        }

        float s[4][4];
        #pragma unroll
        for (int i = 0; i < 4; i++) {
            float2 u0 = upk(s2[i][0]), u1 = upk(s2[i][1]);
            s[i][0] = u0.x; s[i][1] = u0.y; s[i][2] = u1.x; s[i][3] = u1.y;
        }

        // online softmax (reduce over the 16 lanes sharing each row)
        float m_old[4], m_new[4], rs[4];
        #pragma unroll
        for (int i = 0; i < 4; i++) {
            m_old[i] = m_s[(ty << 2) + i];
            float mx = fmaxf(fmaxf(s[i][0], s[i][1]), fmaxf(s[i][2], s[i][3]));
            mx = fmaxf(mx, __shfl_xor_sync(0xffffffffu, mx, 1));
            mx = fmaxf(mx, __shfl_xor_sync(0xffffffffu, mx, 2));
            mx = fmaxf(mx, __shfl_xor_sync(0xffffffffu, mx, 4));
            mx = fmaxf(mx, __shfl_xor_sync(0xffffffffu, mx, 8));
            m_new[i] = fmaxf(m_old[i], mx);
            float sum = 0.f;
            #pragma unroll
            for (int j = 0; j < 4; j++) {
                s[i][j] = __expf(s[i][j] - m_new[i]);
                sum += s[i][j];
            }
            sum += __shfl_xor_sync(0xffffffffu, sum, 1);
            sum += __shfl_xor_sync(0xffffffffu, sum, 2);
            sum += __shfl_xor_sync(0xffffffffu, sum, 4);
            sum += __shfl_xor_sync(0xffffffffu, sum, 8);
            rs[i] = sum;
            #pragma unroll
            for (int j = 0; j < 4; j++)
                p_s[((ty << 2) + i) * PST + (tx << 2) + j] = s[i][j];
        }
        __syncthreads();   // m_s reads done; p_s visible

        if (tx == 0) {
            #pragma unroll
            for (int i = 0; i < 4; i++) {
                int r = (ty << 2) + i;
                float scale = __expf(m_old[i] - m_new[i]);
                sc_s[r] = scale;
                l_s[r]  = l_s[r] * scale + rs[i];
                m_s[r]  = m_new[i];
            }
        }
        __syncthreads();   // sc_s/l_s/m_s updates visible

        // PV: rows (2rp, 2rp+1), cols cg*8..+7, over this thread's 32 keys
        {
            unsigned long long sc0 = dup2(sc_s[2 * rp]);
            unsigned long long sc1 = dup2(sc_s[2 * rp + 1]);
            #pragma unroll
            for (int c = 0; c < 4; c++) {
                o2[0][c] = mul2(o2[0][c], sc0);
                o2[1][c] = mul2(o2[1][c], sc1);
            }
            const int jbase = jh << 5;
            const float* p0 = &p_s[(2 * rp) * PST + jbase];
            const float* p1 = &p_s[(2 * rp + 1) * PST + jbase];
            #pragma unroll 8
            for (int j = 0; j < 32; j++) {
                ulonglong2 vv0 = *(const ulonglong2*)&v_s[jbase + j][cg << 3];
                ulonglong2 vv1 = *(const ulonglong2*)&v_s[jbase + j][(cg << 3) + 4];
                unsigned long long b0 = dup2(p0[j]);
                unsigned long long b1 = dup2(p1[j]);
                o2[0][0] = fma2(vv0.x, b0, o2[0][0]);
                o2[0][1] = fma2(vv0.y, b0, o2[0][1]);
                o2[0][2] = fma2(vv1.x, b0, o2[0][2]);
                o2[0][3] = fma2(vv1.y, b0, o2[0][3]);
                o2[1][0] = fma2(vv0.x, b1, o2[1][0]);
                o2[1][1] = fma2(vv0.y, b1, o2[1][1]);
                o2[1][2] = fma2(vv1.x, b1, o2[1][2]);
                o2[1][3] = fma2(vv1.y, b1, o2[1][3]);
            }
        }
        __syncthreads();   // done with this tile's smem
    }

    // deferred reduction of the two j-halves (reuse p_s as o_red[64][32])
    if (jh == 1) {
        #pragma unroll
        for (int r = 0; r < 2; r++) {
            float2 c0 = upk(o2[r][0]), c1 = upk(o2[r][1]);
            float2 c2 = upk(o2[r][2]), c3 = upk(o2[r][3]);
            float* dst = &p_s[(2 * rp + r) * 32 + (cg << 3)];
            *(float4*)(dst)     = make_float4(c0.x, c0.y, c1.x, c1.y);
            *(float4*)(dst + 4) = make_float4(c2.x, c2.y, c3.x, c3.y);
        }
    }
    __syncthreads();
    if (jh == 0) {
        #pragma unroll
        for (int r = 0; r < 2; r++) {
            int row = 2 * rp + r;
            float inv = 1.f / l_s[row];
            float2 c0 = upk(o2[r][0]), c1 = upk(o2[r][1]);
            float2 c2 = upk(o2[r][2]), c3 = upk(o2[r][3]);
            const float* red = &p_s[row * 32 + (cg << 3)];
            float4 r0 = *(const float4*)(red);
            float4 r1 = *(const float4*)(red + 4);
            size_t og = base + (size_t)(qb * 64 + row) * E_ + (cg << 3);
            float4 o0 = make_float4((c0.x + r0.x) * inv, (c0.y + r0.y) * inv,
                                    (c1.x + r0.z) * inv, (c1.y + r0.w) * inv);
            float4 o1 = make_float4((c2.x + r1.x) * inv, (c2.y + r1.y) * inv,
                                    (c3.x + r1.z) * inv, (c3.y + r1.w) * inv);
            *(float4*)&out[og]     = o0;
            *(float4*)&out[og + 4] = o1;
        }
    }
}

// ---------------- fused residual + LayerNorm --------------------------------
__global__ __launch_bounds__(256) void ln_residual_kernel(
    const float* __restrict__ x, const float* __restrict__ r,
    const float* __restrict__ g, const float* __restrict__ beta,
    float* __restrict__ y)
{
    __shared__ float red[256];
    const int row = blockIdx.x;
    const int tid = threadIdx.x;
    const size_t off = (size_t)row * E_;
    const int c4 = tid << 2;

    float4 xv = *(const float4*)&x[off + c4];
    float4 rv = *(const float4*)&r[off + c4];
    float v0 = xv.x + rv.x, v1 = xv.y + rv.y, v2 = xv.z + rv.z, v3 = xv.w + rv.w;

    red[tid] = v0 + v1 + v2 + v3;
    __syncthreads();
    #pragma unroll
    for (int st = 128; st > 0; st >>= 1) {
        if (tid < st) red[tid] += red[tid + st];
        __syncthreads();
    }
    float mean = red[0] * (1.f / E_);
    __syncthreads();

    float d0 = v0 - mean, d1 = v1 - mean, d2 = v2 - mean, d3 = v3 - mean;
    red[tid] = d0 * d0 + d1 * d1 + d2 * d2 + d3 * d3;
    __syncthreads();
    #pragma unroll
    for (int st = 128; st > 0; st >>= 1) {
        if (tid < st) red[tid] += red[tid + st];
        __syncthreads();
    }
    float rstd = rsqrtf(red[0] * (1.f / E_) + 1e-5f);

    float4 gv = *(const float4*)&g[c4];
    float4 bv = *(const float4*)&beta[c4];
    float4 o;
    o.x = d0 * rstd * gv.x + bv.x;
    o.y = d1 * rstd * gv.y + bv.y;
    o.z = d2 * rstd * gv.z + bv.z;
    o.w = d3 * rstd * gv.w + bv.w;
    *(float4*)&y[off + c4] = o;
}

// ---------------- launcher ---------------------------------------------------
extern "C" void kernel_launch(void* const* d_in, const int* in_sizes, int n_in,
                              void* d_out, int out_size)
{
    const float* x   = (const float*)d_in[0];
    const float* Wq  = (const float*)d_in[1];
    const float* bq  = (const float*)d_in[2];
    const float* Wk  = (const float*)d_in[3];
    const float* bk  = (const float*)d_in[4];
    const float* Wv  = (const float*)d_in[5];
    const float* bv  = (const float*)d_in[6];
    const float* kW  = (const float*)d_in[7];
    const float* Wo  = (const float*)d_in[8];
    const float* bo  = (const float*)d_in[9];
    const float* W1  = (const float*)d_in[10];
    const float* b1  = (const float*)d_in[11];
    const float* W2  = (const float*)d_in[12];
    const float* b2  = (const float*)d_in[13];
    const float* g1  = (const float*)d_in[14];
    const float* be1 = (const float*)d_in[15];
    const float* g2  = (const float*)d_in[16];
    const float* be2 = (const float*)d_in[17];
    float* out = (float*)d_out;

    float *q, *k, *v, *attn, *x1, *ffn;
    cudaGetSymbolAddress((void**)&q,    g_q);
    cudaGetSymbolAddress((void**)&k,    g_k);
    cudaGetSymbolAddress((void**)&v,    g_v);
    cudaGetSymbolAddress((void**)&attn, g_attn);
    cudaGetSymbolAddress((void**)&x1,   g_x1);
    cudaGetSymbolAddress((void**)&ffn,  g_ffn);

    dim3 gE(E_ / 128, M_ / 128);       // N=1024 GEMMs
    dim3 gF(FFN_ / 128, M_ / 128);     // N=4096 GEMM
    dim3 gQKV(E_ / 128, M_ / 128, 3);  // merged QKV

    // QKV projections (one launch)
    qkv_kernel<<<gQKV, 256>>>(x, Wq, bq, q, Wk, bk, k, Wv, bv, v);

    // bilinear-kernel flash attention -> [B,S,E] layout directly
    attention_kernel<<<dim3(S_ / 64, H_, B_), 256>>>(q, k, v, kW, attn);

    // output projection (reuse q as scratch)
    sgemm_bias_kernel<<<gE, 256>>>(attn, Wo, bo, q, E_, E_, 0);

    // residual + LN 1
    ln_residual_kernel<<<M_, 256>>>(x, q, g1, be1, x1);

    // FFN
    sgemm_bias_kernel<<<gF, 256>>>(x1, W1, b1, ffn, FFN_, E_, 1);
    sgemm_bias_kernel<<<gE, 256>>>(ffn, W2, b2, k, E_, FFN_, 0);

    // residual + LN 2 -> final output
    ln_residual_kernel<<<M_, 256>>>(x1, k, g2, be2, out);
}

// round 6
// speedup vs baseline: 1.9091x; 1.5149x over previous
#include <cuda_runtime.h>
#include <math.h>

#define B_   2
#define S_   2048
#define E_   1024
#define H_   32
#define DK_  32
#define FFN_ 4096
#define M_   (B_*S_)   // 4096 rows

// ---------------- scratch (device globals; no allocations allowed) ----------
__device__ float g_q[M_*E_];
__device__ float g_k[M_*E_];
__device__ float g_v[M_*E_];
__device__ float g_attn[M_*E_];
__device__ float g_x1[M_*E_];
__device__ float g_ffn[M_*FFN_];

// ---------------- packed f32x2 helpers (sm_100a) ----------------------------
__device__ __forceinline__ unsigned long long fma2(unsigned long long a,
                                                   unsigned long long b,
                                                   unsigned long long c) {
    unsigned long long d;
    asm("fma.rn.f32x2 %0, %1, %2, %3;" : "=l"(d) : "l"(a), "l"(b), "l"(c));
    return d;
}
__device__ __forceinline__ unsigned long long mul2(unsigned long long a,
                                                   unsigned long long b) {
    unsigned long long d;
    asm("mul.rn.f32x2 %0, %1, %2;" : "=l"(d) : "l"(a), "l"(b));
    return d;
}
__device__ __forceinline__ unsigned long long dup2(float x) {
    unsigned long long d;
    asm("mov.b64 %0, {%1, %1};" : "=l"(d) : "f"(x));
    return d;
}
__device__ __forceinline__ float2 upk(unsigned long long v) {
    float2 r;
    asm("mov.b64 {%0, %1}, %2;" : "=f"(r.x), "=f"(r.y) : "l"(v));
    return r;
}
__device__ __forceinline__ unsigned tf32c(float x) {
    unsigned r;
    asm("cvt.rna.tf32.f32 %0, %1;" : "=r"(r) : "f"(x));
    return r;
}

// ---------------- TF32 tensor-core GEMM ------------------------------------
// C = A[M,K] @ W[K,N] + bias (optional ReLU). 128x128 tile, BK=16,
// 256 threads = 8 warps (2 x 4). Each warp: 64x32 via 4x4 m16n8k8 atoms.
// Smem holds PRE-CONVERTED tf32 bit patterns (cvt done once at staging).
// Double-buffered, pad strides 20 / 132 (conflict-free fragment loads).
#define ASTR 20
#define BSTR 132

__device__ __forceinline__ void mma_tf32(float& c0, float& c1, float& c2, float& c3,
                                         unsigned a0, unsigned a1, unsigned a2, unsigned a3,
                                         unsigned b0, unsigned b1) {
    asm("mma.sync.aligned.m16n8k8.row.col.f32.tf32.tf32.f32 "
        "{%0,%1,%2,%3}, {%4,%5,%6,%7}, {%8,%9}, {%0,%1,%2,%3};"
        : "+f"(c0), "+f"(c1), "+f"(c2), "+f"(c3)
        : "r"(a0), "r"(a1), "r"(a2), "r"(a3), "r"(b0), "r"(b1));
}

__device__ __forceinline__ uint4 tf32c4(float4 v) {
    uint4 r;
    r.x = tf32c(v.x); r.y = tf32c(v.y); r.z = tf32c(v.z); r.w = tf32c(v.w);
    return r;
}

__device__ __forceinline__ void sgemm_body(
    const float* __restrict__ A, const float* __restrict__ W,
    const float* __restrict__ bias, float* __restrict__ C,
    int N, int K, int doRelu)
{
    __shared__ __align__(16) unsigned As[2][128][ASTR];
    __shared__ __align__(16) unsigned Bs[2][16][BSTR];

    const int tid  = threadIdx.x;
    const int lane = tid & 31;
    const int wid  = tid >> 5;
    const int warp_m = wid >> 2;        // 0..1 -> 64-row half
    const int warp_n = wid & 3;         // 0..3 -> 32-col quarter
    const int g = lane >> 2;            // groupID 0..7
    const int t = lane & 3;             // threadID_in_group 0..3
    const int row0 = blockIdx.y * 128;
    const int col0 = blockIdx.x * 128;

    // staging maps
    const int a_row = tid >> 1;             // 0..127
    const int a_cb  = (tid & 1) << 3;       // 0 or 8
    const int b_row = tid >> 4;             // 0..15
    const int b_cb  = (tid & 15) << 3;      // 0..120

    const float* Aptr = A + (size_t)(row0 + a_row) * K + a_cb;
    const float* Wptr = W + (size_t)b_row * N + col0 + b_cb;

    float acc[4][4][4];
    #pragma unroll
    for (int mi = 0; mi < 4; mi++)
        #pragma unroll
        for (int ni = 0; ni < 4; ni++)
            #pragma unroll
            for (int e = 0; e < 4; e++) acc[mi][ni][e] = 0.f;

    {   // preload slice 0 (convert to tf32 at staging)
        *(uint4*)&As[0][a_row][a_cb]     = tf32c4(*(const float4*)(Aptr));
        *(uint4*)&As[0][a_row][a_cb + 4] = tf32c4(*(const float4*)(Aptr + 4));
        *(uint4*)&Bs[0][b_row][b_cb]     = tf32c4(*(const float4*)(Wptr));
        *(uint4*)&Bs[0][b_row][b_cb + 4] = tf32c4(*(const float4*)(Wptr + 4));
    }
    __syncthreads();

    const int nT = K >> 4;
    int buf = 0;
    for (int it = 0; it < nT; it++) {
        float4 av0, av1, bv0, bv1;
        const int has_next = (it + 1 < nT);
        if (has_next) {
            int k0 = (it + 1) << 4;
            av0 = *(const float4*)(Aptr + k0);
            av1 = *(const float4*)(Aptr + k0 + 4);
            bv0 = *(const float4*)(Wptr + (size_t)k0 * N);
            bv1 = *(const float4*)(Wptr + (size_t)k0 * N + 4);
        }

        #pragma unroll
        for (int kk = 0; kk < 16; kk += 8) {
            // B fragments: 4 n-tiles x 2 regs
            unsigned bf[4][2];
            #pragma unroll
            for (int ni = 0; ni < 4; ni++) {
                int col = (warp_n << 5) + (ni << 3) + g;
                bf[ni][0] = Bs[buf][kk + t][col];
                bf[ni][1] = Bs[buf][kk + t + 4][col];
            }
            // A fragments + MMAs per m-tile
            #pragma unroll
            for (int mi = 0; mi < 4; mi++) {
                int row = (warp_m << 6) + (mi << 4) + g;
                unsigned a0 = As[buf][row][kk + t];
                unsigned a1 = As[buf][row + 8][kk + t];
                unsigned a2 = As[buf][row][kk + t + 4];
                unsigned a3 = As[buf][row + 8][kk + t + 4];
                #pragma unroll
                for (int ni = 0; ni < 4; ni++)
                    mma_tf32(acc[mi][ni][0], acc[mi][ni][1],
                             acc[mi][ni][2], acc[mi][ni][3],
                             a0, a1, a2, a3, bf[ni][0], bf[ni][1]);
            }
        }

        if (has_next) {
            int nb = buf ^ 1;
            *(uint4*)&As[nb][a_row][a_cb]     = tf32c4(av0);
            *(uint4*)&As[nb][a_row][a_cb + 4] = tf32c4(av1);
            *(uint4*)&Bs[nb][b_row][b_cb]     = tf32c4(bv0);
            *(uint4*)&Bs[nb][b_row][b_cb + 4] = tf32c4(bv1);
            __syncthreads();
            buf = nb;
        }
    }

    // epilogue: c0,c1 -> (row g, cols 2t,2t+1); c2,c3 -> row g+8
    #pragma unroll
    for (int mi = 0; mi < 4; mi++) {
        int rbase = row0 + (warp_m << 6) + (mi << 4) + g;
        #pragma unroll
        for (int ni = 0; ni < 4; ni++) {
            int c = col0 + (warp_n << 5) + (ni << 3) + (t << 1);
            float2 bv = *(const float2*)&bias[c];
            float2 o0, o1;
            o0.x = acc[mi][ni][0] + bv.x; o0.y = acc[mi][ni][1] + bv.y;
            o1.x = acc[mi][ni][2] + bv.x; o1.y = acc[mi][ni][3] + bv.y;
            if (doRelu) {
                o0.x = fmaxf(o0.x, 0.f); o0.y = fmaxf(o0.y, 0.f);
                o1.x = fmaxf(o1.x, 0.f); o1.y = fmaxf(o1.y, 0.f);
            }
            *(float2*)&C[(size_t)rbase * N + c]       = o0;
            *(float2*)&C[(size_t)(rbase + 8) * N + c] = o1;
        }
    }
}

__global__ __launch_bounds__(256) void sgemm_bias_kernel(
    const float* __restrict__ A, const float* __restrict__ W,
    const float* __restrict__ bias, float* __restrict__ C,
    int N, int K, int doRelu)
{
    sgemm_body(A, W, bias, C, N, K, doRelu);
}

// merged QKV: blockIdx.z picks which projection
__global__ __launch_bounds__(256) void qkv_kernel(
    const float* __restrict__ x,
    const float* __restrict__ Wq, const float* __restrict__ bq, float* __restrict__ q,
    const float* __restrict__ Wk, const float* __restrict__ bk, float* __restrict__ k,
    const float* __restrict__ Wv, const float* __restrict__ bv, float* __restrict__ v)
{
    const float* W; const float* b; float* C;
    if (blockIdx.z == 0)      { W = Wq; b = bq; C = q; }
    else if (blockIdx.z == 1) { W = Wk; b = bk; C = k; }
    else                      { W = Wv; b = bv; C = v; }
    sgemm_body(x, W, b, C, E_, E_, 0);
}

// ---------------- Flash attention with bilinear kernel scaling --------------
// sim[b,h,i,j] = sum_d (q[b,h,i,d]*kernelW[d,h]) * k[b,h,j,d]
// grid: (S/64, H, B), 256 threads. 64q x 64k tiles, online softmax.
// PV phase: j-dim split across 2 thread halves, deferred reduction at end.
#define PST 67   // p_s row stride (floats)
#define VST 36   // v_s row stride

__global__ __launch_bounds__(256) void attention_kernel(
    const float* __restrict__ q, const float* __restrict__ k,
    const float* __restrict__ v, const float* __restrict__ kernelW,
    float* __restrict__ out)
{
    __shared__ __align__(16) float q_s[32][68];   // [d][row]
    __shared__ __align__(16) float k_s[32][68];   // [d][row]
    __shared__ __align__(16) float v_s[64][VST];  // [j][d]
    __shared__ __align__(16) float p_s[64 * PST]; // [row*PST + j]; reused as o_red
    __shared__ float m_s[64], l_s[64], sc_s[64];

    const int tid = threadIdx.x;
    const int tx = tid & 15;        // key-col group (softmax phase)
    const int ty = tid >> 4;        // query-row group (softmax phase)
    const int jh = tid >> 7;            // 0/1: which 32-key half
    const int cg = (tid >> 5) & 3;      // col group
    const int rp = tid & 31;            // row pair

    const int qb = blockIdx.x, h = blockIdx.y, b = blockIdx.z;
    const size_t base = ((size_t)b * S_) * E_ + (size_t)h * DK_;

    #pragma unroll
    for (int it = 0; it < 2; it++) {
        int i  = tid + it * 256;
        int r  = i >> 3;
        int d0 = (i & 7) << 2;
        float4 qv = *(const float4*)&q[base + (size_t)(qb * 64 + r) * E_ + d0];
        q_s[d0 + 0][r] = qv.x * kernelW[(d0 + 0) * H_ + h];
        q_s[d0 + 1][r] = qv.y * kernelW[(d0 + 1) * H_ + h];
        q_s[d0 + 2][r] = qv.z * kernelW[(d0 + 2) * H_ + h];
        q_s[d0 + 3][r] = qv.w * kernelW[(d0 + 3) * H_ + h];
    }
    if (tid < 64) { m_s[tid] = -INFINITY; l_s[tid] = 0.f; }

    unsigned long long o2[2][4];
    #pragma unroll
    for (int r = 0; r < 2; r++)
        #pragma unroll
        for (int c = 0; c < 4; c++) o2[r][c] = 0ull;

    __syncthreads();

    for (int j0 = 0; j0 < S_; j0 += 64) {
        #pragma unroll
        for (int it = 0; it < 2; it++) {
            int i  = tid + it * 256;
            int r  = i >> 3;
            int d0 = (i & 7) << 2;
            size_t g = base + (size_t)(j0 + r) * E_ + d0;
            float4 kv = *(const float4*)&k[g];
            k_s[d0 + 0][r] = kv.x; k_s[d0 + 1][r] = kv.y;
            k_s[d0 + 2][r] = kv.z; k_s[d0 + 3][r] = kv.w;
            *(float4*)&v_s[r][d0] = *(const float4*)&v[g];
        }
        __syncthreads();

        unsigned long long s2[4][2];
        #pragma unroll
        for (int i = 0; i < 4; i++) { s2[i][0] = 0ull; s2[i][1] = 0ull; }

        #pragma unroll
        for (int d = 0; d < 32; d++) {
            float qa[4];
            *(float4*)qa = *(const float4*)&q_s[d][ty << 2];
            ulonglong2 kp = *(const ulonglong2*)&k_s[d][tx << 2];
            #pragma unroll
            for (int i = 0; i < 4; i++) {
                unsigned long long qq = dup2(qa[i]);
                s2[i][0] = fma2(kp.x, qq, s2[i][0]);
                s2[i][1] = fma2(kp.y, qq, s2[i][1]);
            }
        }

        float s[4][4];
        #pragma unroll
        for (int i = 0; i < 4; i++) {
            float2 u0 = upk(s2[i][0]), u1 = upk(s2[i][1]);
            s[i][0] = u0.x; s[i][1] = u0.y; s[i][2] = u1.x; s[i][3] = u1.y;
        }

        float m_old[4], m_new[4], rs[4];
        #pragma unroll
        for (int i = 0; i < 4; i++) {
            m_old[i] = m_s[(ty << 2) + i];
            float mx = fmaxf(fmaxf(s[i][0], s[i][1]), fmaxf(s[i][2], s[i][3]));
            mx = fmaxf(mx, __shfl_xor_sync(0xffffffffu, mx, 1));
            mx = fmaxf(mx, __shfl_xor_sync(0xffffffffu, mx, 2));
            mx = fmaxf(mx, __shfl_xor_sync(0xffffffffu, mx, 4));
            mx = fmaxf(mx, __shfl_xor_sync(0xffffffffu, mx, 8));
            m_new[i] = fmaxf(m_old[i], mx);
            float sum = 0.f;
            #pragma unroll
            for (int j = 0; j < 4; j++) {
                s[i][j] = __expf(s[i][j] - m_new[i]);
                sum += s[i][j];
            }
            sum += __shfl_xor_sync(0xffffffffu, sum, 1);
            sum += __shfl_xor_sync(0xffffffffu, sum, 2);
            sum += __shfl_xor_sync(0xffffffffu, sum, 4);
            sum += __shfl_xor_sync(0xffffffffu, sum, 8);
            rs[i] = sum;
            #pragma unroll
            for (int j = 0; j < 4; j++)
                p_s[((ty << 2) + i) * PST + (tx << 2) + j] = s[i][j];
        }
        __syncthreads();

        if (tx == 0) {
            #pragma unroll
            for (int i = 0; i < 4; i++) {
                int r = (ty << 2) + i;
                float scale = __expf(m_old[i] - m_new[i]);
                sc_s[r] = scale;
                l_s[r]  = l_s[r] * scale + rs[i];
                m_s[r]  = m_new[i];
            }
        }
        __syncthreads();

        {
            unsigned long long sc0 = dup2(sc_s[2 * rp]);
            unsigned long long sc1 = dup2(sc_s[2 * rp + 1]);
            #pragma unroll
            for (int c = 0; c < 4; c++) {
                o2[0][c] = mul2(o2[0][c], sc0);
                o2[1][c] = mul2(o2[1][c], sc1);
            }
            const int jbase = jh << 5;
            const float* p0 = &p_s[(2 * rp) * PST + jbase];
            const float* p1 = &p_s[(2 * rp + 1) * PST + jbase];
            #pragma unroll 8
            for (int j = 0; j < 32; j++) {
                ulonglong2 vv0 = *(const ulonglong2*)&v_s[jbase + j][cg << 3];
                ulonglong2 vv1 = *(const ulonglong2*)&v_s[jbase + j][(cg << 3) + 4];
                unsigned long long b0 = dup2(p0[j]);
                unsigned long long b1 = dup2(p1[j]);
                o2[0][0] = fma2(vv0.x, b0, o2[0][0]);
                o2[0][1] = fma2(vv0.y, b0, o2[0][1]);
                o2[0][2] = fma2(vv1.x, b0, o2[0][2]);
                o2[0][3] = fma2(vv1.y, b0, o2[0][3]);
                o2[1][0] = fma2(vv0.x, b1, o2[1][0]);
                o2[1][1] = fma2(vv0.y, b1, o2[1][1]);
                o2[1][2] = fma2(vv1.x, b1, o2[1][2]);
                o2[1][3] = fma2(vv1.y, b1, o2[1][3]);
            }
        }
        __syncthreads();
    }

    if (jh == 1) {
        #pragma unroll
        for (int r = 0; r < 2; r++) {
            float2 c0 = upk(o2[r][0]), c1 = upk(o2[r][1]);
            float2 c2 = upk(o2[r][2]), c3 = upk(o2[r][3]);
            float* dst = &p_s[(2 * rp + r) * 32 + (cg << 3)];
            *(float4*)(dst)     = make_float4(c0.x, c0.y, c1.x, c1.y);
            *(float4*)(dst + 4) = make_float4(c2.x, c2.y, c3.x, c3.y);
        }
    }
    __syncthreads();
    if (jh == 0) {
        #pragma unroll
        for (int r = 0; r < 2; r++) {
            int row = 2 * rp + r;
            float inv = 1.f / l_s[row];
            float2 c0 = upk(o2[r][0]), c1 = upk(o2[r][1]);
            float2 c2 = upk(o2[r][2]), c3 = upk(o2[r][3]);
            const float* red = &p_s[row * 32 + (cg << 3)];
            float4 r0 = *(const float4*)(red);
            float4 r1 = *(const float4*)(red + 4);
            size_t og = base + (size_t)(qb * 64 + row) * E_ + (cg << 3);
            float4 o0 = make_float4((c0.x + r0.x) * inv, (c0.y + r0.y) * inv,
                                    (c1.x + r0.z) * inv, (c1.y + r0.w) * inv);
            float4 o1 = make_float4((c2.x + r1.x) * inv, (c2.y + r1.y) * inv,
                                    (c3.x + r1.z) * inv, (c3.y + r1.w) * inv);
            *(float4*)&out[og]     = o0;
            *(float4*)&out[og + 4] = o1;
        }
    }
}

// ---------------- fused residual + LayerNorm --------------------------------
__global__ __launch_bounds__(256) void ln_residual_kernel(
    const float* __restrict__ x, const float* __restrict__ r,
    const float* __restrict__ g, const float* __restrict__ beta,
    float* __restrict__ y)
{
    __shared__ float red[256];
    const int row = blockIdx.x;
    const int tid = threadIdx.x;
    const size_t off = (size_t)row * E_;
    const int c4 = tid << 2;

    float4 xv = *(const float4*)&x[off + c4];
    float4 rv = *(const float4*)&r[off + c4];
    float v0 = xv.x + rv.x, v1 = xv.y + rv.y, v2 = xv.z + rv.z, v3 = xv.w + rv.w;

    red[tid] = v0 + v1 + v2 + v3;
    __syncthreads();
    #pragma unroll
    for (int st = 128; st > 0; st >>= 1) {
        if (tid < st) red[tid] += red[tid + st];
        __syncthreads();
    }
    float mean = red[0] * (1.f / E_);
    __syncthreads();

    float d0 = v0 - mean, d1 = v1 - mean, d2 = v2 - mean, d3 = v3 - mean;
    red[tid] = d0 * d0 + d1 * d1 + d2 * d2 + d3 * d3;
    __syncthreads();
    #pragma unroll
    for (int st = 128; st > 0; st >>= 1) {
        if (tid < st) red[tid] += red[tid + st];
        __syncthreads();
    }
    float rstd = rsqrtf(red[0] * (1.f / E_) + 1e-5f);

    float4 gv = *(const float4*)&g[c4];
    float4 bv = *(const float4*)&beta[c4];
    float4 o;
    o.x = d0 * rstd * gv.x + bv.x;
    o.y = d1 * rstd * gv.y + bv.y;
    o.z = d2 * rstd * gv.z + bv.z;
    o.w = d3 * rstd * gv.w + bv.w;
    *(float4*)&y[off + c4] = o;
}

// ---------------- launcher ---------------------------------------------------
extern "C" void kernel_launch(void* const* d_in, const int* in_sizes, int n_in,
                              void* d_out, int out_size)
{
    const float* x   = (const float*)d_in[0];
    const float* Wq  = (const float*)d_in[1];
    const float* bq  = (const float*)d_in[2];
    const float* Wk  = (const float*)d_in[3];
    const float* bk  = (const float*)d_in[4];
    const float* Wv  = (const float*)d_in[5];
    const float* bv  = (const float*)d_in[6];
    const float* kW  = (const float*)d_in[7];
    const float* Wo  = (const float*)d_in[8];
    const float* bo  = (const float*)d_in[9];
    const float* W1  = (const float*)d_in[10];
    const float* b1  = (const float*)d_in[11];
    const float* W2  = (const float*)d_in[12];
    const float* b2  = (const float*)d_in[13];
    const float* g1  = (const float*)d_in[14];
    const float* be1 = (const float*)d_in[15];
    const float* g2  = (const float*)d_in[16];
    const float* be2 = (const float*)d_in[17];
    float* out = (float*)d_out;

    float *q, *k, *v, *attn, *x1, *ffn;
    cudaGetSymbolAddress((void**)&q,    g_q);
    cudaGetSymbolAddress((void**)&k,    g_k);
    cudaGetSymbolAddress((void**)&v,    g_v);
    cudaGetSymbolAddress((void**)&attn, g_attn);
    cudaGetSymbolAddress((void**)&x1,   g_x1);
    cudaGetSymbolAddress((void**)&ffn,  g_ffn);

    dim3 gE(E_ / 128, M_ / 128);       // N=1024 GEMMs
    dim3 gF(FFN_ / 128, M_ / 128);     // N=4096 GEMM
    dim3 gQKV(E_ / 128, M_ / 128, 3);  // merged QKV

    qkv_kernel<<<gQKV, 256>>>(x, Wq, bq, q, Wk, bk, k, Wv, bv, v);

    attention_kernel<<<dim3(S_ / 64, H_, B_), 256>>>(q, k, v, kW, attn);

    sgemm_bias_kernel<<<gE, 256>>>(attn, Wo, bo, q, E_, E_, 0);

    ln_residual_kernel<<<M_, 256>>>(x, q, g1, be1, x1);

    sgemm_bias_kernel<<<gF, 256>>>(x1, W1, b1, ffn, FFN_, E_, 1);
    sgemm_bias_kernel<<<gE, 256>>>(ffn, W2, b2, k, E_, FFN_, 0);

    ln_residual_kernel<<<M_, 256>>>(x1, k, g2, be2, out);
}

// round 9
// speedup vs baseline: 1.9162x; 1.0037x over previous
#include <cuda_runtime.h>
#include <math.h>

#define B_   2
#define S_   2048
#define E_   1024
#define H_   32
#define DK_  32
#define FFN_ 4096
#define M_   (B_*S_)   // 4096 rows

// ---------------- scratch (device globals; no allocations allowed) ----------
__device__ float g_q[M_*E_];
__device__ float g_k[M_*E_];
__device__ float g_v[M_*E_];
__device__ float g_attn[M_*E_];
__device__ float g_x1[M_*E_];
__device__ float g_ffn[M_*FFN_];

// ---------------- packed f32x2 helpers (sm_100a) ----------------------------
__device__ __forceinline__ unsigned long long fma2(unsigned long long a,
                                                   unsigned long long b,
                                                   unsigned long long c) {
    unsigned long long d;
    asm("fma.rn.f32x2 %0, %1, %2, %3;" : "=l"(d) : "l"(a), "l"(b), "l"(c));
    return d;
}
__device__ __forceinline__ unsigned long long mul2(unsigned long long a,
                                                   unsigned long long b) {
    unsigned long long d;
    asm("mul.rn.f32x2 %0, %1, %2;" : "=l"(d) : "l"(a), "l"(b));
    return d;
}
__device__ __forceinline__ unsigned long long dup2(float x) {
    unsigned long long d;
    asm("mov.b64 %0, {%1, %1};" : "=l"(d) : "f"(x));
    return d;
}
__device__ __forceinline__ float2 upk(unsigned long long v) {
    float2 r;
    asm("mov.b64 {%0, %1}, %2;" : "=f"(r.x), "=f"(r.y) : "l"(v));
    return r;
}
__device__ __forceinline__ unsigned tf32c(float x) {
    unsigned r;
    asm("cvt.rna.tf32.f32 %0, %1;" : "=r"(r) : "f"(x));
    return r;
}

// ---------------- TF32 tensor-core GEMM (mma.sync; compute_100-safe) --------
// C = A[M,K] @ W[K,N] + bias (optional ReLU). 128x128 tile, BK=16,
// 256 threads = 8 warps (2 x 4). Each warp: 64x32 via 4x4 m16n8k8 atoms.
// Smem holds PRE-CONVERTED tf32 bit patterns (cvt done once at staging).
// Double-buffered, pad strides 20 / 132 (conflict-free fragment loads).
#define ASTR 20
#define BSTR 132

__device__ __forceinline__ void mma_tf32(float& c0, float& c1, float& c2, float& c3,
                                         unsigned a0, unsigned a1, unsigned a2, unsigned a3,
                                         unsigned b0, unsigned b1) {
    asm("mma.sync.aligned.m16n8k8.row.col.f32.tf32.tf32.f32 "
        "{%0,%1,%2,%3}, {%4,%5,%6,%7}, {%8,%9}, {%0,%1,%2,%3};"
        : "+f"(c0), "+f"(c1), "+f"(c2), "+f"(c3)
        : "r"(a0), "r"(a1), "r"(a2), "r"(a3), "r"(b0), "r"(b1));
}

__device__ __forceinline__ uint4 tf32c4(float4 v) {
    uint4 r;
    r.x = tf32c(v.x); r.y = tf32c(v.y); r.z = tf32c(v.z); r.w = tf32c(v.w);
    return r;
}

__device__ __forceinline__ void sgemm_body(
    const float* __restrict__ A, const float* __restrict__ W,
    const float* __restrict__ bias, float* __restrict__ C,
    int N, int K, int doRelu)
{
    __shared__ __align__(16) unsigned As[2][128][ASTR];
    __shared__ __align__(16) unsigned Bs[2][16][BSTR];

    const int tid  = threadIdx.x;
    const int lane = tid & 31;
    const int wid  = tid >> 5;
    const int warp_m = wid >> 2;        // 0..1 -> 64-row half
    const int warp_n = wid & 3;         // 0..3 -> 32-col quarter
    const int g = lane >> 2;            // groupID 0..7
    const int t = lane & 3;             // threadID_in_group 0..3
    const int row0 = blockIdx.y * 128;
    const int col0 = blockIdx.x * 128;

    // staging maps
    const int a_row = tid >> 1;             // 0..127
    const int a_cb  = (tid & 1) << 3;       // 0 or 8
    const int b_row = tid >> 4;             // 0..15
    const int b_cb  = (tid & 15) << 3;      // 0..120

    const float* Aptr = A + (size_t)(row0 + a_row) * K + a_cb;
    const float* Wptr = W + (size_t)b_row * N + col0 + b_cb;

    float acc[4][4][4];
    #pragma unroll
    for (int mi = 0; mi < 4; mi++)
        #pragma unroll
        for (int ni = 0; ni < 4; ni++)
            #pragma unroll
            for (int e = 0; e < 4; e++) acc[mi][ni][e] = 0.f;

    {   // preload slice 0 (convert to tf32 at staging)
        *(uint4*)&As[0][a_row][a_cb]     = tf32c4(*(const float4*)(Aptr));
        *(uint4*)&As[0][a_row][a_cb + 4] = tf32c4(*(const float4*)(Aptr + 4));
        *(uint4*)&Bs[0][b_row][b_cb]     = tf32c4(*(const float4*)(Wptr));
        *(uint4*)&Bs[0][b_row][b_cb + 4] = tf32c4(*(const float4*)(Wptr + 4));
    }
    __syncthreads();

    const int nT = K >> 4;
    int buf = 0;
    for (int it = 0; it < nT; it++) {
        float4 av0, av1, bv0, bv1;
        const int has_next = (it + 1 < nT);
        if (has_next) {
            int k0 = (it + 1) << 4;
            av0 = *(const float4*)(Aptr + k0);
            av1 = *(const float4*)(Aptr + k0 + 4);
            bv0 = *(const float4*)(Wptr + (size_t)k0 * N);
            bv1 = *(const float4*)(Wptr + (size_t)k0 * N + 4);
        }

        #pragma unroll
        for (int kk = 0; kk < 16; kk += 8) {
            // B fragments: 4 n-tiles x 2 regs
            unsigned bf[4][2];
            #pragma unroll
            for (int ni = 0; ni < 4; ni++) {
                int col = (warp_n << 5) + (ni << 3) + g;
                bf[ni][0] = Bs[buf][kk + t][col];
                bf[ni][1] = Bs[buf][kk + t + 4][col];
            }
            // A fragments + MMAs per m-tile
            #pragma unroll
            for (int mi = 0; mi < 4; mi++) {
                int row = (warp_m << 6) + (mi << 4) + g;
                unsigned a0 = As[buf][row][kk + t];
                unsigned a1 = As[buf][row + 8][kk + t];
                unsigned a2 = As[buf][row][kk + t + 4];
                unsigned a3 = As[buf][row + 8][kk + t + 4];
                #pragma unroll
                for (int ni = 0; ni < 4; ni++)
                    mma_tf32(acc[mi][ni][0], acc[mi][ni][1],
                             acc[mi][ni][2], acc[mi][ni][3],
                             a0, a1, a2, a3, bf[ni][0], bf[ni][1]);
            }
        }

        if (has_next) {
            int nb = buf ^ 1;
            *(uint4*)&As[nb][a_row][a_cb]     = tf32c4(av0);
            *(uint4*)&As[nb][a_row][a_cb + 4] = tf32c4(av1);
            *(uint4*)&Bs[nb][b_row][b_cb]     = tf32c4(bv0);
            *(uint4*)&Bs[nb][b_row][b_cb + 4] = tf32c4(bv1);
            __syncthreads();
            buf = nb;
        }
    }

    // epilogue: c0,c1 -> (row g, cols 2t,2t+1); c2,c3 -> row g+8
    #pragma unroll
    for (int mi = 0; mi < 4; mi++) {
        int rbase = row0 + (warp_m << 6) + (mi << 4) + g;
        #pragma unroll
        for (int ni = 0; ni < 4; ni++) {
            int c = col0 + (warp_n << 5) + (ni << 3) + (t << 1);
            float2 bv = *(const float2*)&bias[c];
            float2 o0, o1;
            o0.x = acc[mi][ni][0] + bv.x; o0.y = acc[mi][ni][1] + bv.y;
            o1.x = acc[mi][ni][2] + bv.x; o1.y = acc[mi][ni][3] + bv.y;
            if (doRelu) {
                o0.x = fmaxf(o0.x, 0.f); o0.y = fmaxf(o0.y, 0.f);
                o1.x = fmaxf(o1.x, 0.f); o1.y = fmaxf(o1.y, 0.f);
            }
            *(float2*)&C[(size_t)rbase * N + c]       = o0;
            *(float2*)&C[(size_t)(rbase + 8) * N + c] = o1;
        }
    }
}

__global__ __launch_bounds__(256) void sgemm_bias_kernel(
    const float* __restrict__ A, const float* __restrict__ W,
    const float* __restrict__ bias, float* __restrict__ C,
    int N, int K, int doRelu)
{
    sgemm_body(A, W, bias, C, N, K, doRelu);
}

// merged QKV: blockIdx.z picks which projection
__global__ __launch_bounds__(256) void qkv_kernel(
    const float* __restrict__ x,
    const float* __restrict__ Wq, const float* __restrict__ bq, float* __restrict__ q,
    const float* __restrict__ Wk, const float* __restrict__ bk, float* __restrict__ k,
    const float* __restrict__ Wv, const float* __restrict__ bv, float* __restrict__ v)
{
    const float* W; const float* b; float* C;
    if (blockIdx.z == 0)      { W = Wq; b = bq; C = q; }
    else if (blockIdx.z == 1) { W = Wk; b = bk; C = k; }
    else                      { W = Wv; b = bv; C = v; }
    sgemm_body(x, W, b, C, E_, E_, 0);
}

// ---------------- Flash attention with bilinear kernel scaling --------------
// sim[b,h,i,j] = sum_d (q[b,h,i,d]*kernelW[d,h]) * k[b,h,j,d]
// grid: (S/64, H, B), 256 threads. 64q x 64k tiles, online softmax.
// m/l state in registers (replicated across the 16 lanes per row).
// Next K/V tile prefetched into registers during compute; 3 syncs per tile.
#define PST 67   // p_s row stride (floats)
#define VST 36   // v_s row stride

__global__ __launch_bounds__(256) void attention_kernel(
    const float* __restrict__ q, const float* __restrict__ k,
    const float* __restrict__ v, const float* __restrict__ kernelW,
    float* __restrict__ out)
{
    __shared__ __align__(16) float q_s[32][68];   // [d][row]
    __shared__ __align__(16) float k_s[32][68];   // [d][row]
    __shared__ __align__(16) float v_s[64][VST];  // [j][d]
    __shared__ __align__(16) float p_s[64 * PST]; // [row*PST + j]; reused as o_red
    __shared__ float l_s[64], sc_s[64];

    const int tid = threadIdx.x;
    const int tx = tid & 15;        // key-col group (softmax phase)
    const int ty = tid >> 4;        // query-row group (softmax phase)
    const int jh = tid >> 7;            // 0/1: which 32-key half (PV phase)
    const int cg = (tid >> 5) & 3;      // col group
    const int rp = tid & 31;            // row pair

    const int qb = blockIdx.x, h = blockIdx.y, b = blockIdx.z;
    const size_t base = ((size_t)b * S_) * E_ + (size_t)h * DK_;

    // per-thread staging coordinates (used for both K/V stage and prefetch)
    const int st_r0  = tid >> 3;                 // 0..31  (it=0)
    const int st_r1  = (tid + 256) >> 3;         // 32..63 (it=1)
    const int st_d0  = (tid & 7) << 2;           // 0,4,...,28

    // load & scale Q tile (64 rows x 32 dims) -> transposed smem
    #pragma unroll
    for (int it = 0; it < 2; it++) {
        int i  = tid + it * 256;
        int r  = i >> 3;
        int d0 = (i & 7) << 2;
        float4 qv = *(const float4*)&q[base + (size_t)(qb * 64 + r) * E_ + d0];
        q_s[d0 + 0][r] = qv.x * kernelW[(d0 + 0) * H_ + h];
        q_s[d0 + 1][r] = qv.y * kernelW[(d0 + 1) * H_ + h];
        q_s[d0 + 2][r] = qv.z * kernelW[(d0 + 2) * H_ + h];
        q_s[d0 + 3][r] = qv.w * kernelW[(d0 + 3) * H_ + h];
    }

    // prologue: stage tile 0 K/V
    {
        size_t g0 = base + (size_t)st_r0 * E_ + st_d0;
        size_t g1 = base + (size_t)st_r1 * E_ + st_d0;
        float4 kv0 = *(const float4*)&k[g0];
        float4 kv1 = *(const float4*)&k[g1];
        k_s[st_d0 + 0][st_r0] = kv0.x; k_s[st_d0 + 1][st_r0] = kv0.y;
        k_s[st_d0 + 2][st_r0] = kv0.z; k_s[st_d0 + 3][st_r0] = kv0.w;
        k_s[st_d0 + 0][st_r1] = kv1.x; k_s[st_d0 + 1][st_r1] = kv1.y;
        k_s[st_d0 + 2][st_r1] = kv1.z; k_s[st_d0 + 3][st_r1] = kv1.w;
        *(float4*)&v_s[st_r0][st_d0] = *(const float4*)&v[g0];
        *(float4*)&v_s[st_r1][st_d0] = *(const float4*)&v[g1];
    }

    // register state
    float m_reg[4], l_reg[4];
    #pragma unroll
    for (int i = 0; i < 4; i++) { m_reg[i] = -INFINITY; l_reg[i] = 0.f; }

    unsigned long long o2[2][4];
    #pragma unroll
    for (int r = 0; r < 2; r++)
        #pragma unroll
        for (int c = 0; c < 4; c++) o2[r][c] = 0ull;

    __syncthreads();

    const int NT = S_ / 64;
    for (int t = 0; t < NT; t++) {
        // prefetch next tile's K/V into registers (latency hidden by compute)
        float4 pkv0, pkv1, pvv0, pvv1;
        const int has_next = (t + 1 < NT);
        if (has_next) {
            size_t g0 = base + (size_t)((t + 1) * 64 + st_r0) * E_ + st_d0;
            size_t g1 = base + (size_t)((t + 1) * 64 + st_r1) * E_ + st_d0;
            pkv0 = *(const float4*)&k[g0];
            pkv1 = *(const float4*)&k[g1];
            pvv0 = *(const float4*)&v[g0];
            pvv1 = *(const float4*)&v[g1];
        }

        // scores: 4 rows x 4 keys per thread, FFMA2 over key pairs
        unsigned long long s2[4][2];
        #pragma unroll
        for (int i = 0; i < 4; i++) { s2[i][0] = 0ull; s2[i][1] = 0ull; }

        #pragma unroll
        for (int d = 0; d < 32; d++) {
            float qa[4];
            *(float4*)qa = *(const float4*)&q_s[d][ty << 2];
            ulonglong2 kp = *(const ulonglong2*)&k_s[d][tx << 2];
            #pragma unroll
            for (int i = 0; i < 4; i++) {
                unsigned long long qq = dup2(qa[i]);
                s2[i][0] = fma2(kp.x, qq, s2[i][0]);
                s2[i][1] = fma2(kp.y, qq, s2[i][1]);
            }
        }

        float s[4][4];
        #pragma unroll
        for (int i = 0; i < 4; i++) {
            float2 u0 = upk(s2[i][0]), u1 = upk(s2[i][1]);
            s[i][0] = u0.x; s[i][1] = u0.y; s[i][2] = u1.x; s[i][3] = u1.y;
        }

        // online softmax (reduce over the 16 lanes sharing each row)
        #pragma unroll
        for (int i = 0; i < 4; i++) {
            float m_old = m_reg[i];
            float mx = fmaxf(fmaxf(s[i][0], s[i][1]), fmaxf(s[i][2], s[i][3]));
            mx = fmaxf(mx, __shfl_xor_sync(0xffffffffu, mx, 1));
            mx = fmaxf(mx, __shfl_xor_sync(0xffffffffu, mx, 2));
            mx = fmaxf(mx, __shfl_xor_sync(0xffffffffu, mx, 4));
            mx = fmaxf(mx, __shfl_xor_sync(0xffffffffu, mx, 8));
            float m_new = fmaxf(m_old, mx);
            float sum = 0.f;
            #pragma unroll
            for (int j = 0; j < 4; j++) {
                s[i][j] = __expf(s[i][j] - m_new);
                sum += s[i][j];
            }
            sum += __shfl_xor_sync(0xffffffffu, sum, 1);
            sum += __shfl_xor_sync(0xffffffffu, sum, 2);
            sum += __shfl_xor_sync(0xffffffffu, sum, 4);
            sum += __shfl_xor_sync(0xffffffffu, sum, 8);
            float scale = __expf(m_old - m_new);
            l_reg[i] = l_reg[i] * scale + sum;
            m_reg[i] = m_new;
            int r = (ty << 2) + i;
            if (tx == 0) sc_s[r] = scale;
            if (t == NT - 1 && tx == 1) l_s[r] = l_reg[i];
            #pragma unroll
            for (int j = 0; j < 4; j++)
                p_s[r * PST + (tx << 2) + j] = s[i][j];
        }
        __syncthreads();   // p_s, sc_s (and final l_s) visible

        // PV: rows (2rp, 2rp+1), cols cg*8..+7, over this thread's 32 keys
        {
            unsigned long long sc0 = dup2(sc_s[2 * rp]);
            unsigned long long sc1 = dup2(sc_s[2 * rp + 1]);
            #pragma unroll
            for (int c = 0; c < 4; c++) {
                o2[0][c] = mul2(o2[0][c], sc0);
                o2[1][c] = mul2(o2[1][c], sc1);
            }
            const int jbase = jh << 5;
            const float* p0 = &p_s[(2 * rp) * PST + jbase];
            const float* p1 = &p_s[(2 * rp + 1) * PST + jbase];
            #pragma unroll 8
            for (int j = 0; j < 32; j++) {
                ulonglong2 vv0 = *(const ulonglong2*)&v_s[jbase + j][cg << 3];
                ulonglong2 vv1 = *(const ulonglong2*)&v_s[jbase + j][(cg << 3) + 4];
                unsigned long long b0 = dup2(p0[j]);
                unsigned long long b1 = dup2(p1[j]);
                o2[0][0] = fma2(vv0.x, b0, o2[0][0]);
                o2[0][1] = fma2(vv0.y, b0, o2[0][1]);
                o2[0][2] = fma2(vv1.x, b0, o2[0][2]);
                o2[0][3] = fma2(vv1.y, b0, o2[0][3]);
                o2[1][0] = fma2(vv0.x, b1, o2[1][0]);
                o2[1][1] = fma2(vv0.y, b1, o2[1][1]);
                o2[1][2] = fma2(vv1.x, b1, o2[1][2]);
                o2[1][3] = fma2(vv1.y, b1, o2[1][3]);
            }
        }
        __syncthreads();   // PV done reading v_s/p_s

        if (has_next) {
            k_s[st_d0 + 0][st_r0] = pkv0.x; k_s[st_d0 + 1][st_r0] = pkv0.y;
            k_s[st_d0 + 2][st_r0] = pkv0.z; k_s[st_d0 + 3][st_r0] = pkv0.w;
            k_s[st_d0 + 0][st_r1] = pkv1.x; k_s[st_d0 + 1][st_r1] = pkv1.y;
            k_s[st_d0 + 2][st_r1] = pkv1.z; k_s[st_d0 + 3][st_r1] = pkv1.w;
            *(float4*)&v_s[st_r0][st_d0] = pvv0;
            *(float4*)&v_s[st_r1][st_d0] = pvv1;
            __syncthreads();   // new K/V visible for next score phase
        }
    }

    // deferred reduction of the two j-halves (reuse p_s as o_red[64][32])
    if (jh == 1) {
        #pragma unroll
        for (int r = 0; r < 2; r++) {
            float2 c0 = upk(o2[r][0]), c1 = upk(o2[r][1]);
            float2 c2 = upk(o2[r][2]), c3 = upk(o2[r][3]);
            float* dst = &p_s[(2 * rp + r) * 32 + (cg << 3)];
            *(float4*)(dst)     = make_float4(c0.x, c0.y, c1.x, c1.y);
            *(float4*)(dst + 4) = make_float4(c2.x, c2.y, c3.x, c3.y);
        }
    }
    __syncthreads();
    if (jh == 0) {
        #pragma unroll
        for (int r = 0; r < 2; r++) {
            int row = 2 * rp + r;
            float inv = 1.f / l_s[row];
            float2 c0 = upk(o2[r][0]), c1 = upk(o2[r][1]);
            float2 c2 = upk(o2[r][2]), c3 = upk(o2[r][3]);
            const float* red = &p_s[row * 32 + (cg << 3)];
            float4 r0 = *(const float4*)(red);
            float4 r1 = *(const float4*)(red + 4);
            size_t og = base + (size_t)(qb * 64 + row) * E_ + (cg << 3);
            float4 o0 = make_float4((c0.x + r0.x) * inv, (c0.y + r0.y) * inv,
                                    (c1.x + r0.z) * inv, (c1.y + r0.w) * inv);
            float4 o1 = make_float4((c2.x + r1.x) * inv, (c2.y + r1.y) * inv,
                                    (c3.x + r1.z) * inv, (c3.y + r1.w) * inv);
            *(float4*)&out[og]     = o0;
            *(float4*)&out[og + 4] = o1;
        }
    }
}

// ---------------- fused residual + LayerNorm --------------------------------
__global__ __launch_bounds__(256) void ln_residual_kernel(
    const float* __restrict__ x, const float* __restrict__ r,
    const float* __restrict__ g, const float* __restrict__ beta,
    float* __restrict__ y)
{
    __shared__ float red[256];
    const int row = blockIdx.x;
    const int tid = threadIdx.x;
    const size_t off = (size_t)row * E_;
    const int c4 = tid << 2;

    float4 xv = *(const float4*)&x[off + c4];
    float4 rv = *(const float4*)&r[off + c4];
    float v0 = xv.x + rv.x, v1 = xv.y + rv.y, v2 = xv.z + rv.z, v3 = xv.w + rv.w;

    red[tid] = v0 + v1 + v2 + v3;
    __syncthreads();
    #pragma unroll
    for (int st = 128; st > 0; st >>= 1) {
        if (tid < st) red[tid] += red[tid + st];
        __syncthreads();
    }
    float mean = red[0] * (1.f / E_);
    __syncthreads();

    float d0 = v0 - mean, d1 = v1 - mean, d2 = v2 - mean, d3 = v3 - mean;
    red[tid] = d0 * d0 + d1 * d1 + d2 * d2 + d3 * d3;
    __syncthreads();
    #pragma unroll
    for (int st = 128; st > 0; st >>= 1) {
        if (tid < st) red[tid] += red[tid + st];
        __syncthreads();
    }
    float rstd = rsqrtf(red[0] * (1.f / E_) + 1e-5f);

    float4 gv = *(const float4*)&g[c4];
    float4 bv = *(const float4*)&beta[c4];
    float4 o;
    o.x = d0 * rstd * gv.x + bv.x;
    o.y = d1 * rstd * gv.y + bv.y;
    o.z = d2 * rstd * gv.z + bv.z;
    o.w = d3 * rstd * gv.w + bv.w;
    *(float4*)&y[off + c4] = o;
}

// ---------------- launcher ---------------------------------------------------
extern "C" void kernel_launch(void* const* d_in, const int* in_sizes, int n_in,
                              void* d_out, int out_size)
{
    const float* x   = (const float*)d_in[0];
    const float* Wq  = (const float*)d_in[1];
    const float* bq  = (const float*)d_in[2];
    const float* Wk  = (const float*)d_in[3];
    const float* bk  = (const float*)d_in[4];
    const float* Wv  = (const float*)d_in[5];
    const float* bv  = (const float*)d_in[6];
    const float* kW  = (const float*)d_in[7];
    const float* Wo  = (const float*)d_in[8];
    const float* bo  = (const float*)d_in[9];
    const float* W1  = (const float*)d_in[10];
    const float* b1  = (const float*)d_in[11];
    const float* W2  = (const float*)d_in[12];
    const float* b2  = (const float*)d_in[13];
    const float* g1  = (const float*)d_in[14];
    const float* be1 = (const float*)d_in[15];
    const float* g2  = (const float*)d_in[16];
    const float* be2 = (const float*)d_in[17];
    float* out = (float*)d_out;

    float *q, *k, *v, *attn, *x1, *ffn;
    cudaGetSymbolAddress((void**)&q,    g_q);
    cudaGetSymbolAddress((void**)&k,    g_k);
    cudaGetSymbolAddress((void**)&v,    g_v);
    cudaGetSymbolAddress((void**)&attn, g_attn);
    cudaGetSymbolAddress((void**)&x1,   g_x1);
    cudaGetSymbolAddress((void**)&ffn,  g_ffn);

    dim3 gE(E_ / 128, M_ / 128);       // N=1024 GEMMs
    dim3 gF(FFN_ / 128, M_ / 128);     // N=4096 GEMM
    dim3 gQKV(E_ / 128, M_ / 128, 3);  // merged QKV

    qkv_kernel<<<gQKV, 256>>>(x, Wq, bq, q, Wk, bk, k, Wv, bv, v);

    attention_kernel<<<dim3(S_ / 64, H_, B_), 256>>>(q, k, v, kW, attn);

    sgemm_bias_kernel<<<gE, 256>>>(attn, Wo, bo, q, E_, E_, 0);

    ln_residual_kernel<<<M_, 256>>>(x, q, g1, be1, x1);

    sgemm_bias_kernel<<<gF, 256>>>(x1, W1, b1, ffn, FFN_, E_, 1);
    sgemm_bias_kernel<<<gE, 256>>>(ffn, W2, b2, k, E_, FFN_, 0);

    ln_residual_kernel<<<M_, 256>>>(x1, k, g2, be2, out);
}